// round 3
// baseline (speedup 1.0000x reference)
#include <cuda_runtime.h>

#define NROWS 8192
#define DDIM  1024
#define HDIM  4096
#define NLAY  5          // NUM_LAYERS + 1
#define NTOT  7168       // 7 * DDIM
#define EPSF  1e-8f

// ---------------- device scratch (allocation-free rule: __device__ globals) ----
__device__ __align__(16) float g_A[DDIM * DDIM];
__device__ __align__(16) float g_B[DDIM * DDIM];          // current B^i (starts as I)
__device__ __align__(16) float g_P[DDIM * DDIM];          // B^i * A
__device__ __align__(16) float g_Wbig[DDIM * NTOT];       // [C0..C4 | M1 | M2]
__device__ __align__(16) float g_bias[NTOT];              // [d0..d4 | v1 | v2]
__device__ __align__(16) float g_c[DDIM];
__device__ __align__(16) float g_u[DDIM];
__device__ __align__(16) float g_w[DDIM];
__device__ __align__(16) float g_out[(size_t)NLAY * NROWS * DDIM];  // out_i scratch
__device__ __align__(16) float g_S[NLAY * NROWS];
__device__ __align__(16) float g_n2[NLAY * NROWS];
__device__ __align__(16) float g_D[DDIM];

// ---------------- helpers ----------------
__device__ __forceinline__ float warp_red(float v) {
    #pragma unroll
    for (int o = 16; o > 0; o >>= 1) v += __shfl_down_sync(0xffffffffu, v, o);
    return v;
}

// ---------------- generic strided SGEMM, 64x64x16 tile, 4x4/thread -----------
__global__ __launch_bounds__(256) void sgemm_gen(
    int K,
    const float* __restrict__ X, int xsm, int xsk,
    const float* __restrict__ Y, int ysk, int ysn,
    float* __restrict__ C, int csm, int csn)
{
    __shared__ float Xs[16][68];
    __shared__ float Ys[16][68];
    const int bm = blockIdx.y * 64, bn = blockIdx.x * 64;
    const int tid = threadIdx.x, tx = tid & 15, ty = tid >> 4;
    float acc[4][4] = {};

    for (int k0 = 0; k0 < K; k0 += 16) {
        if (xsk == 1) {
            #pragma unroll
            for (int i = 0; i < 4; i++) {
                int f = tid + i * 256; int k = f & 15, m = f >> 4;
                Xs[k][m] = X[(size_t)(bm + m) * xsm + (size_t)(k0 + k)];
            }
        } else {
            #pragma unroll
            for (int i = 0; i < 4; i++) {
                int f = tid + i * 256; int m = f & 63, k = f >> 6;
                Xs[k][m] = X[(size_t)(bm + m) * xsm + (size_t)(k0 + k) * xsk];
            }
        }
        if (ysn == 1) {
            #pragma unroll
            for (int i = 0; i < 4; i++) {
                int f = tid + i * 256; int n = f & 63, k = f >> 6;
                Ys[k][n] = Y[(size_t)(k0 + k) * ysk + (size_t)(bn + n)];
            }
        } else {
            #pragma unroll
            for (int i = 0; i < 4; i++) {
                int f = tid + i * 256; int k = f & 15, n = f >> 4;
                Ys[k][n] = Y[(size_t)(k0 + k) * ysk + (size_t)(bn + n) * ysn];
            }
        }
        __syncthreads();
        #pragma unroll
        for (int k = 0; k < 16; k++) {
            float a[4], b[4];
            #pragma unroll
            for (int j = 0; j < 4; j++) a[j] = Xs[k][ty * 4 + j];
            #pragma unroll
            for (int j = 0; j < 4; j++) b[j] = Ys[k][tx * 4 + j];
            #pragma unroll
            for (int i2 = 0; i2 < 4; i2++)
                #pragma unroll
                for (int j2 = 0; j2 < 4; j2++)
                    acc[i2][j2] += a[i2] * b[j2];
        }
        __syncthreads();
    }
    #pragma unroll
    for (int i2 = 0; i2 < 4; i2++)
        #pragma unroll
        for (int j2 = 0; j2 < 4; j2++)
            C[(size_t)(bm + ty * 4 + i2) * csm + (size_t)(bn + tx * 4 + j2) * csn] = acc[i2][j2];
}

// ---------------- big fused GEMM: x(8192x1024) @ Wbig(1024x7168) + bias ------
__global__ __launch_bounds__(256) void sgemm_big(
    const float* __restrict__ X, float* __restrict__ out5, float* __restrict__ out6)
{
    __shared__ float Xs[16][132];
    __shared__ float Ws[16][128];
    const int bn = blockIdx.x * 128;
    const int bm = blockIdx.y * 128;
    const int tid = threadIdx.x;
    const int tx = tid & 15, ty = tid >> 4;
    float acc[8][8] = {};

    for (int k0 = 0; k0 < DDIM; k0 += 16) {
        #pragma unroll
        for (int i = 0; i < 2; i++) {
            int f = tid + i * 256;
            int m = f >> 2, kv = (f & 3) * 4;
            float4 v = *reinterpret_cast<const float4*>(X + (size_t)(bm + m) * DDIM + k0 + kv);
            Xs[kv + 0][m] = v.x; Xs[kv + 1][m] = v.y;
            Xs[kv + 2][m] = v.z; Xs[kv + 3][m] = v.w;
        }
        #pragma unroll
        for (int i = 0; i < 2; i++) {
            int f = tid + i * 256;
            int k = f >> 5, nv = (f & 31) * 4;
            *reinterpret_cast<float4*>(&Ws[k][nv]) =
                *reinterpret_cast<const float4*>(g_Wbig + (size_t)(k0 + k) * NTOT + bn + nv);
        }
        __syncthreads();
        #pragma unroll
        for (int k = 0; k < 16; k++) {
            float a[8], b[8];
            #pragma unroll
            for (int j = 0; j < 4; j++) { a[j] = Xs[k][ty * 4 + j]; a[4 + j] = Xs[k][64 + ty * 4 + j]; }
            #pragma unroll
            for (int j = 0; j < 4; j++) { b[j] = Ws[k][tx * 4 + j]; b[4 + j] = Ws[k][64 + tx * 4 + j]; }
            #pragma unroll
            for (int i2 = 0; i2 < 8; i2++)
                #pragma unroll
                for (int j2 = 0; j2 < 8; j2++)
                    acc[i2][j2] += a[i2] * b[j2];
        }
        __syncthreads();
    }

    const int t = bn >> 10;
    const int nloc = bn & 1023;
    float* base = (t < 5) ? (g_out + (size_t)t * NROWS * DDIM)
                          : ((t == 5) ? out5 : out6);
    #pragma unroll
    for (int i2 = 0; i2 < 8; i2++) {
        int row = bm + ((i2 < 4) ? (ty * 4 + i2) : (64 + ty * 4 + (i2 - 4)));
        #pragma unroll
        for (int j2 = 0; j2 < 8; j2++) {
            int colb = (j2 < 4) ? (tx * 4 + j2) : (64 + tx * 4 + (j2 - 4));
            base[(size_t)row * DDIM + nloc + colb] = acc[i2][j2] + g_bias[bn + colb];
        }
    }
}

// ---------------- small kernels ----------------
__global__ void k_identity() {   // g_B = I  (launch 4096x256)
    int idx = blockIdx.x * 256 + threadIdx.x;
    g_B[idx] = ((idx >> 10) == (idx & 1023)) ? 1.0f : 0.0f;
}

__global__ void k_zero_wbig() {  // launch 28672x256
    size_t idx = (size_t)blockIdx.x * 256 + threadIdx.x;
    g_Wbig[idx] = 0.0f;
}

__global__ void k_zero_small() { // launch 8x1024
    int t = threadIdx.x;
    if (blockIdx.x < 7) g_bias[blockIdx.x * DDIM + t] = 0.0f;
    else { g_u[t] = 0.0f; g_w[t] = 0.0f; g_D[t] = 0.0f; }
}

__global__ void k_c(const float* __restrict__ fc1_b, const float* __restrict__ fc2_W,
                    const float* __restrict__ fc2_b) {  // 1024 blocks x 128
    int j = blockIdx.x;
    float s = 0.0f;
    for (int h = threadIdx.x; h < HDIM; h += 128)
        s += fc2_W[(size_t)j * HDIM + h] * fc1_b[h];
    __shared__ float red[4];
    s = warp_red(s);
    if ((threadIdx.x & 31) == 0) red[threadIdx.x >> 5] = s;
    __syncthreads();
    if (threadIdx.x == 0)
        g_c[j] = red[0] + red[1] + red[2] + red[3] + fc2_b[j];
}

__global__ void k_gemv_u() {     // grid(4,8) x 256 : u = w @ A + c
    int j = blockIdx.x * 256 + threadIdx.x;
    int k0 = blockIdx.y * 128;
    float s = 0.0f;
    #pragma unroll 4
    for (int k = k0; k < k0 + 128; k++) s += g_w[k] * g_A[(size_t)k * DDIM + j];
    if (blockIdx.y == 0) s += g_c[j];
    atomicAdd(&g_u[j], s);
}

__global__ void k_gemv_d(const float* __restrict__ cW, const float* __restrict__ cb,
                         int layer) {  // 1024 blocks x 128 : d_i = u @ cW^T + cb
    int n = blockIdx.x;
    float s = 0.0f;
    for (int k = threadIdx.x; k < DDIM; k += 128) s += g_u[k] * cW[(size_t)n * DDIM + k];
    __shared__ float red[4];
    s = warp_red(s);
    if ((threadIdx.x & 31) == 0) red[threadIdx.x >> 5] = s;
    __syncthreads();
    if (threadIdx.x == 0)
        g_bias[layer * DDIM + n] = red[0] + red[1] + red[2] + red[3] + cb[n];
}

__global__ void k_matupd() {     // 4096x256 : M1 += P ; B -= P
    int idx = blockIdx.x * 256 + threadIdx.x;
    int r = idx >> 10, cidx = idx & 1023;
    float p = g_P[idx];
    g_Wbig[(size_t)r * NTOT + 5 * DDIM + cidx] += p;
    g_B[idx] -= p;
}

__global__ void k_vecupd() {     // 4x256 : v1 += u ; w -= u ; u = 0
    int j = blockIdx.x * 256 + threadIdx.x;
    float u = g_u[j];
    g_bias[5 * DDIM + j] += u;
    g_w[j] -= u;
    g_u[j] = 0.0f;
}

__global__ void k_finalize() {   // 4096x256 : Wbig block6 = B^5 ; bias block6 = w
    int idx = blockIdx.x * 256 + threadIdx.x;
    int r = idx >> 10, cidx = idx & 1023;
    g_Wbig[(size_t)r * NTOT + 6 * DDIM + cidx] = g_B[idx];
    if (idx < DDIM) g_bias[6 * DDIM + idx] = g_w[idx];
}

__global__ void k_rowstats() {   // 5*8192 blocks x 256
    size_t row = blockIdx.x;
    const float* p = g_out + row * DDIM;
    float s = 0.0f, q = 0.0f;
    for (int j = threadIdx.x; j < DDIM; j += 256) {
        float v = p[j];
        s += v; q += v * v;
    }
    __shared__ float rs[8], rq[8];
    s = warp_red(s); q = warp_red(q);
    if ((threadIdx.x & 31) == 0) { rs[threadIdx.x >> 5] = s; rq[threadIdx.x >> 5] = q; }
    __syncthreads();
    if (threadIdx.x == 0) {
        float ts = 0.0f, tq = 0.0f;
        #pragma unroll
        for (int i = 0; i < 8; i++) { ts += rs[i]; tq += rq[i]; }
        g_S[row] = ts;
        g_n2[row] = sqrtf(tq);
    }
}

__global__ void k_loss() {       // grid(4, 64, 5) x 256
    int j = blockIdx.x * 256 + threadIdx.x;
    int t = blockIdx.z;
    int d0 = blockIdx.y * 128;
    int d1 = min(d0 + 128, NROWS - 1);
    const float* base = g_out + (size_t)t * NROWS * DDIM;
    const float* Sb = g_S + t * NROWS;
    const float* Nb = g_n2 + t * NROWS;

    float o = base[(size_t)d0 * DDIM + j];
    float prev = o * Sb[d0] / fmaxf(fabsf(o) * 32.0f * Nb[d0], EPSF);
    float acc = 0.0f;
    for (int r = d0 + 1; r <= d1; r++) {
        float ov = base[(size_t)r * DDIM + j];
        float cur = ov * Sb[r] / fmaxf(fabsf(ov) * 32.0f * Nb[r], EPSF);
        acc += fabsf(cur - prev);
        prev = cur;
    }
    atomicAdd(&g_D[j], acc);
}

__global__ void k_broadcast(float* __restrict__ loss) {  // 4096x256
    int idx = blockIdx.x * 256 + threadIdx.x;
    loss[idx] = g_D[idx & 1023];
}

// ---------------- launch ----------------
extern "C" void kernel_launch(void* const* d_in, const int* in_sizes, int n_in,
                              void* d_out, int out_size) {
    const float* x      = (const float*)d_in[0];
    const float* fc1_W  = (const float*)d_in[1];
    const float* fc1_b  = (const float*)d_in[2];
    const float* fc2_W  = (const float*)d_in[3];
    const float* fc2_b  = (const float*)d_in[4];
    const float* comp_W = (const float*)d_in[5];
    const float* comp_b = (const float*)d_in[6];

    float* out    = (float*)d_out;
    float* o_inv  = out;
    float* o_nxt  = out + (size_t)NROWS * DDIM;
    float* o_loss = out + 2 * (size_t)NROWS * DDIM;

    float *pA, *pB, *pP, *pW;
    cudaGetSymbolAddress((void**)&pA, g_A);
    cudaGetSymbolAddress((void**)&pB, g_B);
    cudaGetSymbolAddress((void**)&pP, g_P);
    cudaGetSymbolAddress((void**)&pW, g_Wbig);

    // init
    k_identity<<<4096, 256>>>();
    k_zero_wbig<<<28672, 256>>>();
    k_zero_small<<<8, 1024>>>();
    k_c<<<1024, 128>>>(fc1_b, fc2_W, fc2_b);

    // A = fc1_W^T @ fc2_W^T   (A[i][j] = sum_h fc1_W[h][i] * fc2_W[j][h])
    sgemm_gen<<<dim3(16, 16), 256>>>(HDIM,
        fc1_W, 1, DDIM,
        fc2_W, 1, HDIM,
        pA, DDIM, 1);

    for (int i = 0; i < NLAY; i++) {
        // P = B^i @ A
        sgemm_gen<<<dim3(16, 16), 256>>>(DDIM,
            pB, DDIM, 1,
            pA, DDIM, 1,
            pP, DDIM, 1);
        // C_i = P @ comp_W[i]^T  -> Wbig block i
        sgemm_gen<<<dim3(16, 16), 256>>>(DDIM,
            pP, DDIM, 1,
            comp_W + (size_t)i * DDIM * DDIM, 1, DDIM,
            pW + i * DDIM, NTOT, 1);
        // u = w @ A + c ; d_i = u @ comp_W[i]^T + comp_b[i]
        k_gemv_u<<<dim3(4, 8), 256>>>();
        k_gemv_d<<<1024, 128>>>(comp_W + (size_t)i * DDIM * DDIM, comp_b + i * DDIM, i);
        // M1 += P ; B -= P ; v1 += u ; w -= u ; u = 0
        k_matupd<<<4096, 256>>>();
        k_vecupd<<<4, 256>>>();
    }
    k_finalize<<<4096, 256>>>();

    // the one big GEMM: [out0..out4 | inv_total | nxt] = x @ Wbig + bias
    sgemm_big<<<dim3(NTOT / 128, NROWS / 128), 256>>>(x, o_inv, o_nxt);

    // loss pipeline
    k_rowstats<<<NLAY * NROWS, 256>>>();
    k_loss<<<dim3(4, 64, NLAY), 256>>>();
    k_broadcast<<<4096, 256>>>(o_loss);
}

// round 6
// speedup vs baseline: 1.4963x; 1.4963x over previous
#include <cuda_runtime.h>
#include <cuda_bf16.h>
#include <cstdint>

#define NROWS 8192
#define DDIM  1024
#define HDIM  4096
#define NLAY  5          // NUM_LAYERS + 1
#define NTOT  7168       // 7 * DDIM
#define EPSF  1e-8f

// ---------------- device scratch (allocation-free rule: __device__ globals) ----
__device__ __align__(16) float g_A[DDIM * DDIM];
__device__ __align__(16) float g_B[DDIM * DDIM];          // current B^i (starts as I)
__device__ __align__(16) float g_P[DDIM * DDIM];          // B^i * A
__device__ __align__(16) float g_Wbig[DDIM * NTOT];       // [C0..C4 | M1 | M2]
__device__ __align__(16) float g_bias[NTOT];              // [d0..d4 | v1 | v2]
__device__ __align__(16) float g_c[DDIM];
__device__ __align__(16) float g_u[DDIM];
__device__ __align__(16) float g_w[DDIM];
__device__ __align__(16) float g_out[(size_t)NLAY * NROWS * DDIM];  // out_i scratch
__device__ __align__(16) float g_S[NLAY * NROWS];
__device__ __align__(16) float g_n2[NLAY * NROWS];
__device__ __align__(16) float g_D[DDIM];
// split-bf16 operands for the tensor-core GEMM
__device__ __align__(16) __nv_bfloat16 g_Xhi[(size_t)NROWS * DDIM];
__device__ __align__(16) __nv_bfloat16 g_Xlo[(size_t)NROWS * DDIM];
__device__ __align__(16) __nv_bfloat16 g_WhiT[(size_t)NTOT * DDIM];  // [N][K]
__device__ __align__(16) __nv_bfloat16 g_WloT[(size_t)NTOT * DDIM];

// ---------------- PTX helpers (base compute_103 ISA only) ----------------
__device__ __forceinline__ uint32_t smem_u32(const void* p) {
    uint32_t a;
    asm("{ .reg .u64 t; cvta.to.shared.u64 t, %1; cvt.u32.u64 %0, t; }" : "=r"(a) : "l"(p));
    return a;
}
__device__ __forceinline__ void cp16(uint32_t saddr, const void* gaddr) {
    asm volatile("cp.async.cg.shared.global [%0], [%1], 16;" :: "r"(saddr), "l"(gaddr));
}
#define CP_COMMIT() asm volatile("cp.async.commit_group;" ::: "memory")
#define CP_WAIT1()  asm volatile("cp.async.wait_group 1;" ::: "memory")
#define CP_WAIT0()  asm volatile("cp.async.wait_group 0;" ::: "memory")

__device__ __forceinline__ void ldsm4(uint32_t& r0, uint32_t& r1, uint32_t& r2, uint32_t& r3,
                                      uint32_t addr) {
    asm volatile("ldmatrix.sync.aligned.m8n8.x4.shared.b16 {%0,%1,%2,%3}, [%4];"
                 : "=r"(r0), "=r"(r1), "=r"(r2), "=r"(r3) : "r"(addr));
}
__device__ __forceinline__ void mma16816(float* c, const uint32_t* a, const uint32_t* b) {
    asm volatile(
        "mma.sync.aligned.m16n8k16.row.col.f32.bf16.bf16.f32 "
        "{%0,%1,%2,%3}, {%4,%5,%6,%7}, {%8,%9}, {%0,%1,%2,%3};"
        : "+f"(c[0]), "+f"(c[1]), "+f"(c[2]), "+f"(c[3])
        : "r"(a[0]), "r"(a[1]), "r"(a[2]), "r"(a[3]), "r"(b[0]), "r"(b[1]));
}

__device__ __forceinline__ float warp_red(float v) {
    #pragma unroll
    for (int o = 16; o > 0; o >>= 1) v += __shfl_down_sync(0xffffffffu, v, o);
    return v;
}

// ================= split-bf16 mma.sync big GEMM ==============================
// out[m][n] = sum_k (Xhi+Xlo)[m][k]*(Whi+Wlo)[k][n] (lo*lo dropped), fp32 accum
// CTA tile 128x128, K-chunk 32, 8 warps of 32x64, double-buffered cp.async.
// SMEM row stride 80B -> ldmatrix conflict-free without swizzle.
#define ROWB    80
#define TILE_B  (128 * ROWB)            // 10240 per split-tile
#define STAGE_B (4 * TILE_B)            // Ahi|Alo|Bhi|Blo = 40960
#define DSMEM_BYTES (2 * STAGE_B)       // 81920

__global__ __launch_bounds__(256, 2) void gemm_mma(
    float* __restrict__ out5, float* __restrict__ out6)
{
    extern __shared__ char sm[];
    const int tid = threadIdx.x;
    const int wid = tid >> 5, lane = tid & 31;
    const int bm = blockIdx.y * 128;
    const int bn = blockIdx.x * 128;
    const int wm = (wid & 3) * 32;      // warp row offset in CTA tile
    const int wn = (wid >> 2) * 64;     // warp col offset in CTA tile
    const uint32_t smbase = smem_u32(sm);

    // ---- stage loader: 2048 x 16B cp.async per stage (8 per thread) ----
    auto load_stage = [&](int c, int b) {
        const uint32_t sb = smbase + b * STAGE_B;
        const int k0 = c * 32;
        #pragma unroll
        for (int i = 0; i < 2; i++) {
            int s = tid + i * 256;          // 0..511
            int row = s >> 2, seg = s & 3;
            size_t g = (size_t)(bm + row) * DDIM + k0 + seg * 8;
            uint32_t off = (uint32_t)(row * ROWB + seg * 16);
            cp16(sb + off,              g_Xhi + g);
            cp16(sb + TILE_B + off,     g_Xlo + g);
        }
        #pragma unroll
        for (int i = 0; i < 2; i++) {
            int s = tid + i * 256;
            int row = s >> 2, seg = s & 3;
            size_t g = (size_t)(bn + row) * DDIM + k0 + seg * 8;
            uint32_t off = (uint32_t)(row * ROWB + seg * 16);
            cp16(sb + 2 * TILE_B + off, g_WhiT + g);
            cp16(sb + 3 * TILE_B + off, g_WloT + g);
        }
    };

    float acc[2][8][4] = {};

    // per-lane ldmatrix address components
    const int arow = wm + (lane & 15);
    const int aseg = (lane >> 4) & 1;
    const int brow = wn + (lane & 7) + ((lane & 16) ? 8 : 0);
    const int bseg = (lane >> 3) & 1;

    load_stage(0, 0);
    CP_COMMIT();

    for (int c = 0; c < 32; c++) {
        if (c + 1 < 32) {
            load_stage(c + 1, (c + 1) & 1);
            CP_COMMIT();
            CP_WAIT1();
        } else {
            CP_WAIT0();
        }
        __syncthreads();

        const uint32_t sb = smbase + (c & 1) * STAGE_B;
        #pragma unroll
        for (int ks = 0; ks < 2; ks++) {
            uint32_t ah[2][4], al[2][4];
            #pragma unroll
            for (int mt = 0; mt < 2; mt++) {
                uint32_t addr = sb + (uint32_t)((arow + mt * 16) * ROWB + (2 * ks + aseg) * 16);
                ldsm4(ah[mt][0], ah[mt][1], ah[mt][2], ah[mt][3], addr);
                ldsm4(al[mt][0], al[mt][1], al[mt][2], al[mt][3], addr + TILE_B);
            }
            uint32_t bf[8][2];
            #pragma unroll
            for (int i = 0; i < 4; i++) {
                uint32_t addr = sb + 2 * TILE_B +
                    (uint32_t)((brow + i * 16) * ROWB + (2 * ks + bseg) * 16);
                uint32_t r0, r1, r2, r3;
                ldsm4(r0, r1, r2, r3, addr);
                bf[2 * i][0] = r0; bf[2 * i][1] = r1;
                bf[2 * i + 1][0] = r2; bf[2 * i + 1][1] = r3;
            }
            #pragma unroll
            for (int mt = 0; mt < 2; mt++)
                #pragma unroll
                for (int nt = 0; nt < 8; nt++) {
                    mma16816(acc[mt][nt], ah[mt], bf[nt]);   // hi*hi
                }
            #pragma unroll
            for (int mt = 0; mt < 2; mt++)
                #pragma unroll
                for (int nt = 0; nt < 8; nt++) {
                    mma16816(acc[mt][nt], al[mt], bf[nt]);   // lo*hi
                }
            #pragma unroll
            for (int i = 0; i < 4; i++) {                    // reload B as lo
                uint32_t addr = sb + 3 * TILE_B +
                    (uint32_t)((brow + i * 16) * ROWB + (2 * ks + bseg) * 16);
                uint32_t r0, r1, r2, r3;
                ldsm4(r0, r1, r2, r3, addr);
                bf[2 * i][0] = r0; bf[2 * i][1] = r1;
                bf[2 * i + 1][0] = r2; bf[2 * i + 1][1] = r3;
            }
            #pragma unroll
            for (int mt = 0; mt < 2; mt++)
                #pragma unroll
                for (int nt = 0; nt < 8; nt++) {
                    mma16816(acc[mt][nt], ah[mt], bf[nt]);   // hi*lo
                }
        }
        __syncthreads();
    }

    // ---- epilogue: bias add + route to [out0..4 | inv | nxt] ----
    const int t = bn >> 10;                    // CTA tile never straddles 1024-col blocks
    float* dst = (t < 5) ? (g_out + (size_t)t * NROWS * DDIM)
                         : ((t == 5) ? out5 : out6);
    const int gq = lane >> 2, q = (lane & 3) * 2;
    #pragma unroll
    for (int mt = 0; mt < 2; mt++) {
        int row0 = bm + wm + mt * 16 + gq;
        #pragma unroll
        for (int nt = 0; nt < 8; nt++) {
            int col = bn + wn + nt * 8 + q;
            int cl = col & 1023;
            float b0 = g_bias[col], b1 = g_bias[col + 1];
            float2 v0 = { acc[mt][nt][0] + b0, acc[mt][nt][1] + b1 };
            float2 v1 = { acc[mt][nt][2] + b0, acc[mt][nt][3] + b1 };
            *(float2*)(dst + (size_t)row0 * DDIM + cl) = v0;
            *(float2*)(dst + (size_t)(row0 + 8) * DDIM + cl) = v1;
        }
    }
}

// ================= split kernels ============================================
__global__ void k_splitX(const float* __restrict__ x) {   // grid 8192 x 256
    int row = blockIdx.x, t = threadIdx.x;
    size_t o = (size_t)row * DDIM + t * 4;
    float4 v = *(const float4*)(x + o);
    __nv_bfloat16 h0 = __float2bfloat16_rn(v.x), h1 = __float2bfloat16_rn(v.y);
    __nv_bfloat16 h2 = __float2bfloat16_rn(v.z), h3 = __float2bfloat16_rn(v.w);
    g_Xhi[o + 0] = h0; g_Xhi[o + 1] = h1; g_Xhi[o + 2] = h2; g_Xhi[o + 3] = h3;
    g_Xlo[o + 0] = __float2bfloat16_rn(v.x - __bfloat162float(h0));
    g_Xlo[o + 1] = __float2bfloat16_rn(v.y - __bfloat162float(h1));
    g_Xlo[o + 2] = __float2bfloat16_rn(v.z - __bfloat162float(h2));
    g_Xlo[o + 3] = __float2bfloat16_rn(v.w - __bfloat162float(h3));
}

__global__ void k_splitWT() {   // grid (224, 32) x (32,8) : WT[n][k] = Wbig[k][n]
    __shared__ float tb[32][33];
    int n0 = blockIdx.x * 32, k0 = blockIdx.y * 32;
    int tx = threadIdx.x, ty = threadIdx.y;
    #pragma unroll
    for (int i = 0; i < 4; i++)
        tb[ty + i * 8][tx] = g_Wbig[(size_t)(k0 + ty + i * 8) * NTOT + n0 + tx];
    __syncthreads();
    #pragma unroll
    for (int i = 0; i < 4; i++) {
        int r = ty + i * 8;
        float v = tb[tx][r];
        __nv_bfloat16 hi = __float2bfloat16_rn(v);
        size_t o = (size_t)(n0 + r) * DDIM + k0 + tx;
        g_WhiT[o] = hi;
        g_WloT[o] = __float2bfloat16_rn(v - __bfloat162float(hi));
    }
}

// ---------------- generic strided SGEMM, 64x64x16 tile, 4x4/thread -----------
__global__ __launch_bounds__(256) void sgemm_gen(
    int K,
    const float* __restrict__ X, int xsm, int xsk,
    const float* __restrict__ Y, int ysk, int ysn,
    float* __restrict__ C, int csm, int csn)
{
    __shared__ float Xs[16][68];
    __shared__ float Ys[16][68];
    const int bm = blockIdx.y * 64, bn = blockIdx.x * 64;
    const int tid = threadIdx.x, tx = tid & 15, ty = tid >> 4;
    float acc[4][4] = {};

    for (int k0 = 0; k0 < K; k0 += 16) {
        if (xsk == 1) {
            #pragma unroll
            for (int i = 0; i < 4; i++) {
                int f = tid + i * 256; int k = f & 15, m = f >> 4;
                Xs[k][m] = X[(size_t)(bm + m) * xsm + (size_t)(k0 + k)];
            }
        } else {
            #pragma unroll
            for (int i = 0; i < 4; i++) {
                int f = tid + i * 256; int m = f & 63, k = f >> 6;
                Xs[k][m] = X[(size_t)(bm + m) * xsm + (size_t)(k0 + k) * xsk];
            }
        }
        if (ysn == 1) {
            #pragma unroll
            for (int i = 0; i < 4; i++) {
                int f = tid + i * 256; int n = f & 63, k = f >> 6;
                Ys[k][n] = Y[(size_t)(k0 + k) * ysk + (size_t)(bn + n)];
            }
        } else {
            #pragma unroll
            for (int i = 0; i < 4; i++) {
                int f = tid + i * 256; int k = f & 15, n = f >> 4;
                Ys[k][n] = Y[(size_t)(k0 + k) * ysk + (size_t)(bn + n) * ysn];
            }
        }
        __syncthreads();
        #pragma unroll
        for (int k = 0; k < 16; k++) {
            float a[4], b[4];
            #pragma unroll
            for (int j = 0; j < 4; j++) a[j] = Xs[k][ty * 4 + j];
            #pragma unroll
            for (int j = 0; j < 4; j++) b[j] = Ys[k][tx * 4 + j];
            #pragma unroll
            for (int i2 = 0; i2 < 4; i2++)
                #pragma unroll
                for (int j2 = 0; j2 < 4; j2++)
                    acc[i2][j2] += a[i2] * b[j2];
        }
        __syncthreads();
    }
    #pragma unroll
    for (int i2 = 0; i2 < 4; i2++)
        #pragma unroll
        for (int j2 = 0; j2 < 4; j2++)
            C[(size_t)(bm + ty * 4 + i2) * csm + (size_t)(bn + tx * 4 + j2) * csn] = acc[i2][j2];
}

// ---------------- small kernels ----------------
__global__ void k_identity() {
    int idx = blockIdx.x * 256 + threadIdx.x;
    g_B[idx] = ((idx >> 10) == (idx & 1023)) ? 1.0f : 0.0f;
}
__global__ void k_zero_wbig() {
    size_t idx = (size_t)blockIdx.x * 256 + threadIdx.x;
    g_Wbig[idx] = 0.0f;
}
__global__ void k_zero_small() {
    int t = threadIdx.x;
    if (blockIdx.x < 7) g_bias[blockIdx.x * DDIM + t] = 0.0f;
    else { g_u[t] = 0.0f; g_w[t] = 0.0f; g_D[t] = 0.0f; }
}
__global__ void k_c(const float* __restrict__ fc1_b, const float* __restrict__ fc2_W,
                    const float* __restrict__ fc2_b) {
    int j = blockIdx.x;
    float s = 0.0f;
    for (int h = threadIdx.x; h < HDIM; h += 128)
        s += fc2_W[(size_t)j * HDIM + h] * fc1_b[h];
    __shared__ float red[4];
    s = warp_red(s);
    if ((threadIdx.x & 31) == 0) red[threadIdx.x >> 5] = s;
    __syncthreads();
    if (threadIdx.x == 0)
        g_c[j] = red[0] + red[1] + red[2] + red[3] + fc2_b[j];
}
__global__ void k_gemv_u() {
    int j = blockIdx.x * 256 + threadIdx.x;
    int k0 = blockIdx.y * 128;
    float s = 0.0f;
    #pragma unroll 4
    for (int k = k0; k < k0 + 128; k++) s += g_w[k] * g_A[(size_t)k * DDIM + j];
    if (blockIdx.y == 0) s += g_c[j];
    atomicAdd(&g_u[j], s);
}
__global__ void k_gemv_d(const float* __restrict__ cW, const float* __restrict__ cb,
                         int layer) {
    int n = blockIdx.x;
    float s = 0.0f;
    for (int k = threadIdx.x; k < DDIM; k += 128) s += g_u[k] * cW[(size_t)n * DDIM + k];
    __shared__ float red[4];
    s = warp_red(s);
    if ((threadIdx.x & 31) == 0) red[threadIdx.x >> 5] = s;
    __syncthreads();
    if (threadIdx.x == 0)
        g_bias[layer * DDIM + n] = red[0] + red[1] + red[2] + red[3] + cb[n];
}
__global__ void k_matupd() {
    int idx = blockIdx.x * 256 + threadIdx.x;
    int r = idx >> 10, cidx = idx & 1023;
    float p = g_P[idx];
    g_Wbig[(size_t)r * NTOT + 5 * DDIM + cidx] += p;
    g_B[idx] -= p;
}
__global__ void k_vecupd() {
    int j = blockIdx.x * 256 + threadIdx.x;
    float u = g_u[j];
    g_bias[5 * DDIM + j] += u;
    g_w[j] -= u;
    g_u[j] = 0.0f;
}
__global__ void k_finalize() {
    int idx = blockIdx.x * 256 + threadIdx.x;
    int r = idx >> 10, cidx = idx & 1023;
    g_Wbig[(size_t)r * NTOT + 6 * DDIM + cidx] = g_B[idx];
    if (idx < DDIM) g_bias[6 * DDIM + idx] = g_w[idx];
}
__global__ void k_rowstats() {
    size_t row = blockIdx.x;
    const float* p = g_out + row * DDIM;
    float s = 0.0f, q = 0.0f;
    for (int j = threadIdx.x; j < DDIM; j += 256) {
        float v = p[j];
        s += v; q += v * v;
    }
    __shared__ float rs[8], rq[8];
    s = warp_red(s); q = warp_red(q);
    if ((threadIdx.x & 31) == 0) { rs[threadIdx.x >> 5] = s; rq[threadIdx.x >> 5] = q; }
    __syncthreads();
    if (threadIdx.x == 0) {
        float ts = 0.0f, tq = 0.0f;
        #pragma unroll
        for (int i = 0; i < 8; i++) { ts += rs[i]; tq += rq[i]; }
        g_S[row] = ts;
        g_n2[row] = sqrtf(tq);
    }
}
__global__ void k_loss() {
    int j = blockIdx.x * 256 + threadIdx.x;
    int t = blockIdx.z;
    int d0 = blockIdx.y * 128;
    int d1 = min(d0 + 128, NROWS - 1);
    const float* base = g_out + (size_t)t * NROWS * DDIM;
    const float* Sb = g_S + t * NROWS;
    const float* Nb = g_n2 + t * NROWS;

    float o = base[(size_t)d0 * DDIM + j];
    float prev = o * Sb[d0] / fmaxf(fabsf(o) * 32.0f * Nb[d0], EPSF);
    float acc = 0.0f;
    for (int r = d0 + 1; r <= d1; r++) {
        float ov = base[(size_t)r * DDIM + j];
        float cur = ov * Sb[r] / fmaxf(fabsf(ov) * 32.0f * Nb[r], EPSF);
        acc += fabsf(cur - prev);
        prev = cur;
    }
    atomicAdd(&g_D[j], acc);
}
__global__ void k_broadcast(float* __restrict__ loss) {
    int idx = blockIdx.x * 256 + threadIdx.x;
    loss[idx] = g_D[idx & 1023];
}

// ---------------- launch ----------------
extern "C" void kernel_launch(void* const* d_in, const int* in_sizes, int n_in,
                              void* d_out, int out_size) {
    const float* x      = (const float*)d_in[0];
    const float* fc1_W  = (const float*)d_in[1];
    const float* fc1_b  = (const float*)d_in[2];
    const float* fc2_W  = (const float*)d_in[3];
    const float* fc2_b  = (const float*)d_in[4];
    const float* comp_W = (const float*)d_in[5];
    const float* comp_b = (const float*)d_in[6];

    float* out    = (float*)d_out;
    float* o_inv  = out;
    float* o_nxt  = out + (size_t)NROWS * DDIM;
    float* o_loss = out + 2 * (size_t)NROWS * DDIM;

    float *pA, *pB, *pP, *pW;
    cudaGetSymbolAddress((void**)&pA, g_A);
    cudaGetSymbolAddress((void**)&pB, g_B);
    cudaGetSymbolAddress((void**)&pP, g_P);
    cudaGetSymbolAddress((void**)&pW, g_Wbig);

    static bool attr_set = false;
    if (!attr_set) {
        cudaFuncSetAttribute(gemm_mma, cudaFuncAttributeMaxDynamicSharedMemorySize, DSMEM_BYTES);
        attr_set = true;
    }

    // init
    k_identity<<<4096, 256>>>();
    k_zero_wbig<<<28672, 256>>>();
    k_zero_small<<<8, 1024>>>();
    k_c<<<1024, 128>>>(fc1_b, fc2_W, fc2_b);
    k_splitX<<<NROWS, 256>>>(x);

    // A = fc1_W^T @ fc2_W^T   (A[i][j] = sum_h fc1_W[h][i] * fc2_W[j][h])
    sgemm_gen<<<dim3(16, 16), 256>>>(HDIM,
        fc1_W, 1, DDIM,
        fc2_W, 1, HDIM,
        pA, DDIM, 1);

    for (int i = 0; i < NLAY; i++) {
        sgemm_gen<<<dim3(16, 16), 256>>>(DDIM,
            pB, DDIM, 1,
            pA, DDIM, 1,
            pP, DDIM, 1);
        sgemm_gen<<<dim3(16, 16), 256>>>(DDIM,
            pP, DDIM, 1,
            comp_W + (size_t)i * DDIM * DDIM, 1, DDIM,
            pW + i * DDIM, NTOT, 1);
        k_gemv_u<<<dim3(4, 8), 256>>>();
        k_gemv_d<<<1024, 128>>>(comp_W + (size_t)i * DDIM * DDIM, comp_b + i * DDIM, i);
        k_matupd<<<4096, 256>>>();
        k_vecupd<<<4, 256>>>();
    }
    k_finalize<<<4096, 256>>>();

    // split+transpose Wbig for the tensor-core GEMM
    k_splitWT<<<dim3(NTOT / 32, DDIM / 32), dim3(32, 8)>>>();

    // the one big tensor-core GEMM: [out0..out4 | inv_total | nxt] = x @ Wbig + bias
    gemm_mma<<<dim3(NTOT / 128, NROWS / 128), 256, DSMEM_BYTES>>>(o_inv, o_nxt);

    // loss pipeline
    k_rowstats<<<NLAY * NROWS, 256>>>();
    k_loss<<<dim3(4, 64, NLAY), 256>>>();
    k_broadcast<<<4096, 256>>>(o_loss);
}

// round 10
// speedup vs baseline: 2.5135x; 1.6798x over previous
#include <cuda_runtime.h>
#include <cuda_bf16.h>
#include <cstdint>

#define NROWS 8192
#define DDIM  1024
#define HDIM  4096
#define NLAY  5          // NUM_LAYERS + 1
#define NTOT  7168       // 7 * DDIM
#define EPSF  1e-8f
#define DD    (DDIM * DDIM)

// ---------------- device scratch (allocation-free rule: __device__ globals) ----
__device__ __align__(16) float g_A[DD];
__device__ __align__(16) float g_B[DD];                   // current B^i (starts as I)
__device__ __align__(16) float g_P[DD];                   // B^i * A
__device__ __align__(16) float g_Wbig[DDIM * NTOT];       // [C0..C4 | M1 | M2]
__device__ __align__(16) float g_bias[NTOT];              // [d0..d4 | v1 | v2]
__device__ __align__(16) float g_c[DDIM];
__device__ __align__(16) float g_u[DDIM];
__device__ __align__(16) float g_w[DDIM];
__device__ __align__(16) float g_out[(size_t)NLAY * NROWS * DDIM];  // out_i scratch
__device__ __align__(16) float g_S[NLAY * NROWS];
__device__ __align__(16) float g_n2[NLAY * NROWS];
__device__ __align__(16) float g_D[DDIM];
// split-bf16 operands for the big tensor-core GEMM
__device__ __align__(16) __nv_bfloat16 g_Xhi[(size_t)NROWS * DDIM];
__device__ __align__(16) __nv_bfloat16 g_Xlo[(size_t)NROWS * DDIM];
__device__ __align__(16) __nv_bfloat16 g_WhiT[(size_t)NTOT * DDIM];  // [N][K]
__device__ __align__(16) __nv_bfloat16 g_WloT[(size_t)NTOT * DDIM];
// split-bf16 operands for the precompute chain
__device__ __align__(16) __nv_bfloat16 g_f1Th[(size_t)DDIM * HDIM]; // fc1^T [D][H]
__device__ __align__(16) __nv_bfloat16 g_f1Tl[(size_t)DDIM * HDIM];
__device__ __align__(16) __nv_bfloat16 g_f2h[(size_t)DDIM * HDIM];  // fc2 [D][H]
__device__ __align__(16) __nv_bfloat16 g_f2l[(size_t)DDIM * HDIM];
__device__ __align__(16) __nv_bfloat16 g_ATh[DD];                   // A^T
__device__ __align__(16) __nv_bfloat16 g_ATl[DD];
__device__ __align__(16) __nv_bfloat16 g_Bsh[DD];                   // split of B
__device__ __align__(16) __nv_bfloat16 g_Bsl[DD];
__device__ __align__(16) __nv_bfloat16 g_Psh[DD];                   // split of P
__device__ __align__(16) __nv_bfloat16 g_Psl[DD];
__device__ __align__(16) __nv_bfloat16 g_cwh[(size_t)NLAY * DD];    // comp_W split
__device__ __align__(16) __nv_bfloat16 g_cwl[(size_t)NLAY * DD];

// ---------------- PTX helpers (base compute_103 ISA only) ----------------
__device__ __forceinline__ uint32_t smem_u32(const void* p) {
    uint32_t a;
    asm("{ .reg .u64 t; cvta.to.shared.u64 t, %1; cvt.u32.u64 %0, t; }" : "=r"(a) : "l"(p));
    return a;
}
__device__ __forceinline__ void cp16(uint32_t saddr, const void* gaddr) {
    asm volatile("cp.async.cg.shared.global [%0], [%1], 16;" :: "r"(saddr), "l"(gaddr));
}
#define CP_COMMIT() asm volatile("cp.async.commit_group;" ::: "memory")
#define CP_WAIT1()  asm volatile("cp.async.wait_group 1;" ::: "memory")
#define CP_WAIT0()  asm volatile("cp.async.wait_group 0;" ::: "memory")

__device__ __forceinline__ void ldsm4(uint32_t& r0, uint32_t& r1, uint32_t& r2, uint32_t& r3,
                                      uint32_t addr) {
    asm volatile("ldmatrix.sync.aligned.m8n8.x4.shared.b16 {%0,%1,%2,%3}, [%4];"
                 : "=r"(r0), "=r"(r1), "=r"(r2), "=r"(r3) : "r"(addr));
}
__device__ __forceinline__ void mma16816(float* c, const uint32_t* a, const uint32_t* b) {
    asm volatile(
        "mma.sync.aligned.m16n8k16.row.col.f32.bf16.bf16.f32 "
        "{%0,%1,%2,%3}, {%4,%5,%6,%7}, {%8,%9}, {%0,%1,%2,%3};"
        : "+f"(c[0]), "+f"(c[1]), "+f"(c[2]), "+f"(c[3])
        : "r"(a[0]), "r"(a[1]), "r"(a[2]), "r"(a[3]), "r"(b[0]), "r"(b[1]));
}
__device__ __forceinline__ float warp_red(float v) {
    #pragma unroll
    for (int o = 16; o > 0; o >>= 1) v += __shfl_down_sync(0xffffffffu, v, o);
    return v;
}

#define ROWB 80

// ================= split-bf16 mma.sync big GEMM (128x128 CTA) ================
#define TILE_B  (128 * ROWB)            // 10240 per split-tile
#define STAGE_B (4 * TILE_B)            // Ahi|Alo|Bhi|Blo = 40960
#define DSMEM_BYTES (2 * STAGE_B)       // 81920

__global__ __launch_bounds__(256, 2) void gemm_mma(
    float* __restrict__ out5, float* __restrict__ out6)
{
    extern __shared__ char sm[];
    const int tid = threadIdx.x;
    const int wid = tid >> 5, lane = tid & 31;
    const int bm = blockIdx.y * 128;
    const int bn = blockIdx.x * 128;
    const int wm = (wid & 3) * 32;
    const int wn = (wid >> 2) * 64;
    const uint32_t smbase = smem_u32(sm);

    auto load_stage = [&](int c, int b) {
        const uint32_t sb = smbase + b * STAGE_B;
        const int k0 = c * 32;
        #pragma unroll
        for (int i = 0; i < 2; i++) {
            int s = tid + i * 256;
            int row = s >> 2, seg = s & 3;
            size_t g = (size_t)(bm + row) * DDIM + k0 + seg * 8;
            uint32_t off = (uint32_t)(row * ROWB + seg * 16);
            cp16(sb + off,              g_Xhi + g);
            cp16(sb + TILE_B + off,     g_Xlo + g);
        }
        #pragma unroll
        for (int i = 0; i < 2; i++) {
            int s = tid + i * 256;
            int row = s >> 2, seg = s & 3;
            size_t g = (size_t)(bn + row) * DDIM + k0 + seg * 8;
            uint32_t off = (uint32_t)(row * ROWB + seg * 16);
            cp16(sb + 2 * TILE_B + off, g_WhiT + g);
            cp16(sb + 3 * TILE_B + off, g_WloT + g);
        }
    };

    float acc[2][8][4] = {};
    const int arow = wm + (lane & 15);
    const int aseg = (lane >> 4) & 1;
    const int brow = wn + (lane & 7) + ((lane & 16) ? 8 : 0);
    const int bseg = (lane >> 3) & 1;

    load_stage(0, 0);
    CP_COMMIT();

    for (int c = 0; c < 32; c++) {
        if (c + 1 < 32) {
            load_stage(c + 1, (c + 1) & 1);
            CP_COMMIT();
            CP_WAIT1();
        } else {
            CP_WAIT0();
        }
        __syncthreads();

        const uint32_t sb = smbase + (c & 1) * STAGE_B;
        #pragma unroll
        for (int ks = 0; ks < 2; ks++) {
            uint32_t ah[2][4], al[2][4];
            #pragma unroll
            for (int mt = 0; mt < 2; mt++) {
                uint32_t addr = sb + (uint32_t)((arow + mt * 16) * ROWB + (2 * ks + aseg) * 16);
                ldsm4(ah[mt][0], ah[mt][1], ah[mt][2], ah[mt][3], addr);
                ldsm4(al[mt][0], al[mt][1], al[mt][2], al[mt][3], addr + TILE_B);
            }
            uint32_t bf[8][2];
            #pragma unroll
            for (int i = 0; i < 4; i++) {
                uint32_t addr = sb + 2 * TILE_B +
                    (uint32_t)((brow + i * 16) * ROWB + (2 * ks + bseg) * 16);
                uint32_t r0, r1, r2, r3;
                ldsm4(r0, r1, r2, r3, addr);
                bf[2 * i][0] = r0; bf[2 * i][1] = r1;
                bf[2 * i + 1][0] = r2; bf[2 * i + 1][1] = r3;
            }
            #pragma unroll
            for (int mt = 0; mt < 2; mt++)
                #pragma unroll
                for (int nt = 0; nt < 8; nt++) mma16816(acc[mt][nt], ah[mt], bf[nt]);
            #pragma unroll
            for (int mt = 0; mt < 2; mt++)
                #pragma unroll
                for (int nt = 0; nt < 8; nt++) mma16816(acc[mt][nt], al[mt], bf[nt]);
            #pragma unroll
            for (int i = 0; i < 4; i++) {
                uint32_t addr = sb + 3 * TILE_B +
                    (uint32_t)((brow + i * 16) * ROWB + (2 * ks + bseg) * 16);
                uint32_t r0, r1, r2, r3;
                ldsm4(r0, r1, r2, r3, addr);
                bf[2 * i][0] = r0; bf[2 * i][1] = r1;
                bf[2 * i + 1][0] = r2; bf[2 * i + 1][1] = r3;
            }
            #pragma unroll
            for (int mt = 0; mt < 2; mt++)
                #pragma unroll
                for (int nt = 0; nt < 8; nt++) mma16816(acc[mt][nt], ah[mt], bf[nt]);
        }
        __syncthreads();
    }

    const int t = bn >> 10;
    float* dst = (t < 5) ? (g_out + (size_t)t * NROWS * DDIM)
                         : ((t == 5) ? out5 : out6);
    const int gq = lane >> 2, q = (lane & 3) * 2;
    #pragma unroll
    for (int mt = 0; mt < 2; mt++) {
        int row0 = bm + wm + mt * 16 + gq;
        #pragma unroll
        for (int nt = 0; nt < 8; nt++) {
            int col = bn + wn + nt * 8 + q;
            int cl = col & 1023;
            float b0 = g_bias[col], b1 = g_bias[col + 1];
            float2 v0 = { acc[mt][nt][0] + b0, acc[mt][nt][1] + b1 };
            float2 v1 = { acc[mt][nt][2] + b0, acc[mt][nt][3] + b1 };
            *(float2*)(dst + (size_t)row0 * DDIM + cl) = v0;
            *(float2*)(dst + (size_t)(row0 + 8) * DDIM + cl) = v1;
        }
    }
}

// ================= split-bf16 mma.sync square GEMM (64x64 CTA) ===============
// C[m][n] = sum_k (Ah+Al)[m][k]*(Bh+Bl)[n][k]  (lo*lo dropped), fp32 accum.
// Optionally also emits split-bf16 of C (Ch/Cl, row-major stride ldc).
#define SQT_B   (64 * ROWB)             // 5120
#define SQ_STAGE (4 * SQT_B)            // 20480

__global__ __launch_bounds__(128) void gemm_sq(
    int K,
    const __nv_bfloat16* __restrict__ Ah, const __nv_bfloat16* __restrict__ Al,
    const __nv_bfloat16* __restrict__ Bh, const __nv_bfloat16* __restrict__ Bl,
    float* __restrict__ C, int ldc,
    __nv_bfloat16* __restrict__ Ch, __nv_bfloat16* __restrict__ Cl)
{
    __shared__ __align__(16) char sm[2 * SQ_STAGE];
    const int tid = threadIdx.x;
    const int wid = tid >> 5, lane = tid & 31;
    const int bm = blockIdx.y * 64;
    const int bn = blockIdx.x * 64;
    const int wm = (wid & 1) * 32;
    const int wn = (wid >> 1) * 32;
    const uint32_t smbase = smem_u32(sm);

    auto load_stage = [&](int c, int b) {
        const uint32_t sb = smbase + b * SQ_STAGE;
        const int k0 = c * 32;
        #pragma unroll
        for (int i = 0; i < 2; i++) {
            int s = tid + i * 128;              // 0..255
            int row = s >> 2, seg = s & 3;
            uint32_t off = (uint32_t)(row * ROWB + seg * 16);
            size_t ga = (size_t)(bm + row) * K + k0 + seg * 8;
            size_t gb = (size_t)(bn + row) * K + k0 + seg * 8;
            cp16(sb + off,              Ah + ga);
            cp16(sb + SQT_B + off,      Al + ga);
            cp16(sb + 2 * SQT_B + off,  Bh + gb);
            cp16(sb + 3 * SQT_B + off,  Bl + gb);
        }
    };

    float acc[2][4][4] = {};
    const int arow = wm + (lane & 15);
    const int aseg = (lane >> 4) & 1;
    const int brow = wn + (lane & 7) + ((lane & 16) ? 8 : 0);
    const int bseg = (lane >> 3) & 1;
    const int nchunks = K >> 5;

    load_stage(0, 0);
    CP_COMMIT();

    for (int c = 0; c < nchunks; c++) {
        if (c + 1 < nchunks) {
            load_stage(c + 1, (c + 1) & 1);
            CP_COMMIT();
            CP_WAIT1();
        } else {
            CP_WAIT0();
        }
        __syncthreads();

        const uint32_t sb = smbase + (c & 1) * SQ_STAGE;
        #pragma unroll
        for (int ks = 0; ks < 2; ks++) {
            uint32_t ah[2][4], al[2][4];
            #pragma unroll
            for (int mt = 0; mt < 2; mt++) {
                uint32_t addr = sb + (uint32_t)((arow + mt * 16) * ROWB + (2 * ks + aseg) * 16);
                ldsm4(ah[mt][0], ah[mt][1], ah[mt][2], ah[mt][3], addr);
                ldsm4(al[mt][0], al[mt][1], al[mt][2], al[mt][3], addr + SQT_B);
            }
            uint32_t bf[4][2];
            #pragma unroll
            for (int i = 0; i < 2; i++) {
                uint32_t addr = sb + 2 * SQT_B +
                    (uint32_t)((brow + i * 16) * ROWB + (2 * ks + bseg) * 16);
                uint32_t r0, r1, r2, r3;
                ldsm4(r0, r1, r2, r3, addr);
                bf[2 * i][0] = r0; bf[2 * i][1] = r1;
                bf[2 * i + 1][0] = r2; bf[2 * i + 1][1] = r3;
            }
            #pragma unroll
            for (int mt = 0; mt < 2; mt++)
                #pragma unroll
                for (int nt = 0; nt < 4; nt++) mma16816(acc[mt][nt], ah[mt], bf[nt]);
            #pragma unroll
            for (int mt = 0; mt < 2; mt++)
                #pragma unroll
                for (int nt = 0; nt < 4; nt++) mma16816(acc[mt][nt], al[mt], bf[nt]);
            #pragma unroll
            for (int i = 0; i < 2; i++) {
                uint32_t addr = sb + 3 * SQT_B +
                    (uint32_t)((brow + i * 16) * ROWB + (2 * ks + bseg) * 16);
                uint32_t r0, r1, r2, r3;
                ldsm4(r0, r1, r2, r3, addr);
                bf[2 * i][0] = r0; bf[2 * i][1] = r1;
                bf[2 * i + 1][0] = r2; bf[2 * i + 1][1] = r3;
            }
            #pragma unroll
            for (int mt = 0; mt < 2; mt++)
                #pragma unroll
                for (int nt = 0; nt < 4; nt++) mma16816(acc[mt][nt], ah[mt], bf[nt]);
        }
        __syncthreads();
    }

    const int gq = lane >> 2, q = (lane & 3) * 2;
    const bool do_split = (Ch != nullptr);
    #pragma unroll
    for (int mt = 0; mt < 2; mt++) {
        #pragma unroll
        for (int nt = 0; nt < 4; nt++) {
            int col = bn + wn + nt * 8 + q;
            #pragma unroll
            for (int half = 0; half < 2; half++) {
                int row = bm + wm + mt * 16 + gq + half * 8;
                float v0 = acc[mt][nt][2 * half + 0];
                float v1 = acc[mt][nt][2 * half + 1];
                *(float2*)(C + (size_t)row * ldc + col) = make_float2(v0, v1);
                if (do_split) {
                    __nv_bfloat16 h0 = __float2bfloat16_rn(v0);
                    __nv_bfloat16 h1 = __float2bfloat16_rn(v1);
                    __nv_bfloat162 hh; hh.x = h0; hh.y = h1;
                    __nv_bfloat162 ll;
                    ll.x = __float2bfloat16_rn(v0 - __bfloat162float(h0));
                    ll.y = __float2bfloat16_rn(v1 - __bfloat162float(h1));
                    *(__nv_bfloat162*)(Ch + (size_t)row * ldc + col) = hh;
                    *(__nv_bfloat162*)(Cl + (size_t)row * ldc + col) = ll;
                }
            }
        }
    }
}

// ================= split / transpose kernels ================================
__global__ void k_splitX(const float* __restrict__ x) {   // grid 8192 x 256
    int row = blockIdx.x, t = threadIdx.x;
    size_t o = (size_t)row * DDIM + t * 4;
    float4 v = *(const float4*)(x + o);
    __nv_bfloat16 h0 = __float2bfloat16_rn(v.x), h1 = __float2bfloat16_rn(v.y);
    __nv_bfloat16 h2 = __float2bfloat16_rn(v.z), h3 = __float2bfloat16_rn(v.w);
    g_Xhi[o + 0] = h0; g_Xhi[o + 1] = h1; g_Xhi[o + 2] = h2; g_Xhi[o + 3] = h3;
    g_Xlo[o + 0] = __float2bfloat16_rn(v.x - __bfloat162float(h0));
    g_Xlo[o + 1] = __float2bfloat16_rn(v.y - __bfloat162float(h1));
    g_Xlo[o + 2] = __float2bfloat16_rn(v.z - __bfloat162float(h2));
    g_Xlo[o + 3] = __float2bfloat16_rn(v.w - __bfloat162float(h3));
}

// straight split: dst hi/lo = split(src), n elems (multiple of 1024)
__global__ void k_split(const float* __restrict__ src, size_t n,
                        __nv_bfloat16* __restrict__ dh, __nv_bfloat16* __restrict__ dl)
{
    size_t i = ((size_t)blockIdx.x * 256 + threadIdx.x) * 4;
    if (i >= n) return;
    float4 v = *(const float4*)(src + i);
    __nv_bfloat16 h0 = __float2bfloat16_rn(v.x), h1 = __float2bfloat16_rn(v.y);
    __nv_bfloat16 h2 = __float2bfloat16_rn(v.z), h3 = __float2bfloat16_rn(v.w);
    dh[i + 0] = h0; dh[i + 1] = h1; dh[i + 2] = h2; dh[i + 3] = h3;
    dl[i + 0] = __float2bfloat16_rn(v.x - __bfloat162float(h0));
    dl[i + 1] = __float2bfloat16_rn(v.y - __bfloat162float(h1));
    dl[i + 2] = __float2bfloat16_rn(v.z - __bfloat162float(h2));
    dl[i + 3] = __float2bfloat16_rn(v.w - __bfloat162float(h3));
}

// transpose-split: dst[c][r] = src[r][c]; src is [R][Ccols]; grid (Ccols/32, R/32)
__global__ void k_tsplit(const float* __restrict__ src, int R, int Ccols,
                         __nv_bfloat16* __restrict__ dh, __nv_bfloat16* __restrict__ dl)
{
    __shared__ float tb[32][33];
    int c0 = blockIdx.x * 32, r0 = blockIdx.y * 32;
    int tx = threadIdx.x, ty = threadIdx.y;
    #pragma unroll
    for (int i = 0; i < 4; i++)
        tb[ty + i * 8][tx] = src[(size_t)(r0 + ty + i * 8) * Ccols + c0 + tx];
    __syncthreads();
    #pragma unroll
    for (int i = 0; i < 4; i++) {
        int cc = ty + i * 8;
        float v = tb[tx][cc];                     // = src[r0+tx][c0+cc]
        __nv_bfloat16 hi = __float2bfloat16_rn(v);
        size_t o = (size_t)(c0 + cc) * R + r0 + tx;
        dh[o] = hi;
        dl[o] = __float2bfloat16_rn(v - __bfloat162float(hi));
    }
}

__global__ void k_splitWT() {   // grid (224, 32) x (32,8) : WT[n][k] = Wbig[k][n]
    __shared__ float tb[32][33];
    int n0 = blockIdx.x * 32, k0 = blockIdx.y * 32;
    int tx = threadIdx.x, ty = threadIdx.y;
    #pragma unroll
    for (int i = 0; i < 4; i++)
        tb[ty + i * 8][tx] = g_Wbig[(size_t)(k0 + ty + i * 8) * NTOT + n0 + tx];
    __syncthreads();
    #pragma unroll
    for (int i = 0; i < 4; i++) {
        int r = ty + i * 8;
        float v = tb[tx][r];
        __nv_bfloat16 hi = __float2bfloat16_rn(v);
        size_t o = (size_t)(n0 + r) * DDIM + k0 + tx;
        g_WhiT[o] = hi;
        g_WloT[o] = __float2bfloat16_rn(v - __bfloat162float(hi));
    }
}

// ---------------- small kernels ----------------
__global__ void k_identity() {   // B = I (fp32 + split)
    int idx = blockIdx.x * 256 + threadIdx.x;
    float d = ((idx >> 10) == (idx & 1023)) ? 1.0f : 0.0f;
    g_B[idx] = d;
    g_Bsh[idx] = __float2bfloat16_rn(d);
    g_Bsl[idx] = __float2bfloat16_rn(0.0f);
}
__global__ void k_zero_m1() {    // zero only the M1 accumulation block
    int idx = blockIdx.x * 256 + threadIdx.x;
    int r = idx >> 10, c = idx & 1023;
    g_Wbig[(size_t)r * NTOT + 5 * DDIM + c] = 0.0f;
}
__global__ void k_zero_small() {
    int t = threadIdx.x;
    if (blockIdx.x < 7) g_bias[blockIdx.x * DDIM + t] = 0.0f;
    else { g_u[t] = 0.0f; g_w[t] = 0.0f; g_D[t] = 0.0f; }
}
__global__ void k_c(const float* __restrict__ fc1_b, const float* __restrict__ fc2_W,
                    const float* __restrict__ fc2_b) {
    int j = blockIdx.x;
    float s = 0.0f;
    for (int h = threadIdx.x; h < HDIM; h += 128)
        s += fc2_W[(size_t)j * HDIM + h] * fc1_b[h];
    __shared__ float red[4];
    s = warp_red(s);
    if ((threadIdx.x & 31) == 0) red[threadIdx.x >> 5] = s;
    __syncthreads();
    if (threadIdx.x == 0)
        g_c[j] = red[0] + red[1] + red[2] + red[3] + fc2_b[j];
}
__global__ void k_gemv_u() {
    int j = blockIdx.x * 256 + threadIdx.x;
    int k0 = blockIdx.y * 128;
    float s = 0.0f;
    #pragma unroll 4
    for (int k = k0; k < k0 + 128; k++) s += g_w[k] * g_A[(size_t)k * DDIM + j];
    if (blockIdx.y == 0) s += g_c[j];
    atomicAdd(&g_u[j], s);
}
__global__ void k_gemv_d(const float* __restrict__ cW, const float* __restrict__ cb,
                         int layer) {
    int n = blockIdx.x;
    float s = 0.0f;
    for (int k = threadIdx.x; k < DDIM; k += 128) s += g_u[k] * cW[(size_t)n * DDIM + k];
    __shared__ float red[4];
    s = warp_red(s);
    if ((threadIdx.x & 31) == 0) red[threadIdx.x >> 5] = s;
    __syncthreads();
    if (threadIdx.x == 0)
        g_bias[layer * DDIM + n] = red[0] + red[1] + red[2] + red[3] + cb[n];
}
__global__ void k_matupd() {     // B -= P (+re-split) ; M1 += P
    int idx = blockIdx.x * 256 + threadIdx.x;
    int r = idx >> 10, cidx = idx & 1023;
    float p = g_P[idx];
    float b = g_B[idx] - p;
    g_B[idx] = b;
    __nv_bfloat16 hi = __float2bfloat16_rn(b);
    g_Bsh[idx] = hi;
    g_Bsl[idx] = __float2bfloat16_rn(b - __bfloat162float(hi));
    g_Wbig[(size_t)r * NTOT + 5 * DDIM + cidx] += p;
}
__global__ void k_vecupd() {
    int j = blockIdx.x * 256 + threadIdx.x;
    float u = g_u[j];
    g_bias[5 * DDIM + j] += u;
    g_w[j] -= u;
    g_u[j] = 0.0f;
}
__global__ void k_finalize() {
    int idx = blockIdx.x * 256 + threadIdx.x;
    int r = idx >> 10, cidx = idx & 1023;
    g_Wbig[(size_t)r * NTOT + 6 * DDIM + cidx] = g_B[idx];
    if (idx < DDIM) g_bias[6 * DDIM + idx] = g_w[idx];
}
__global__ void k_rowstats() {
    size_t row = blockIdx.x;
    const float* p = g_out + row * DDIM;
    float s = 0.0f, q = 0.0f;
    for (int j = threadIdx.x; j < DDIM; j += 256) {
        float v = p[j];
        s += v; q += v * v;
    }
    __shared__ float rs[8], rq[8];
    s = warp_red(s); q = warp_red(q);
    if ((threadIdx.x & 31) == 0) { rs[threadIdx.x >> 5] = s; rq[threadIdx.x >> 5] = q; }
    __syncthreads();
    if (threadIdx.x == 0) {
        float ts = 0.0f, tq = 0.0f;
        #pragma unroll
        for (int i = 0; i < 8; i++) { ts += rs[i]; tq += rq[i]; }
        g_S[row] = ts;
        g_n2[row] = sqrtf(tq);
    }
}
__global__ void k_loss() {
    int j = blockIdx.x * 256 + threadIdx.x;
    int t = blockIdx.z;
    int d0 = blockIdx.y * 128;
    int d1 = min(d0 + 128, NROWS - 1);
    const float* base = g_out + (size_t)t * NROWS * DDIM;
    const float* Sb = g_S + t * NROWS;
    const float* Nb = g_n2 + t * NROWS;

    float o = base[(size_t)d0 * DDIM + j];
    float prev = o * Sb[d0] / fmaxf(fabsf(o) * 32.0f * Nb[d0], EPSF);
    float acc = 0.0f;
    for (int r = d0 + 1; r <= d1; r++) {
        float ov = base[(size_t)r * DDIM + j];
        float cur = ov * Sb[r] / fmaxf(fabsf(ov) * 32.0f * Nb[r], EPSF);
        acc += fabsf(cur - prev);
        prev = cur;
    }
    atomicAdd(&g_D[j], acc);
}
__global__ void k_broadcast(float* __restrict__ loss) {
    int idx = blockIdx.x * 256 + threadIdx.x;
    loss[idx] = g_D[idx & 1023];
}

// ---------------- launch ----------------
extern "C" void kernel_launch(void* const* d_in, const int* in_sizes, int n_in,
                              void* d_out, int out_size) {
    const float* x      = (const float*)d_in[0];
    const float* fc1_W  = (const float*)d_in[1];
    const float* fc1_b  = (const float*)d_in[2];
    const float* fc2_W  = (const float*)d_in[3];
    const float* fc2_b  = (const float*)d_in[4];
    const float* comp_W = (const float*)d_in[5];
    const float* comp_b = (const float*)d_in[6];

    float* out    = (float*)d_out;
    float* o_inv  = out;
    float* o_nxt  = out + (size_t)NROWS * DDIM;
    float* o_loss = out + 2 * (size_t)NROWS * DDIM;

    float *pA, *pP, *pW;
    cudaGetSymbolAddress((void**)&pA, g_A);
    cudaGetSymbolAddress((void**)&pP, g_P);
    cudaGetSymbolAddress((void**)&pW, g_Wbig);
    __nv_bfloat16 *pf1Th, *pf1Tl, *pf2h, *pf2l, *pATh, *pATl;
    __nv_bfloat16 *pBsh, *pBsl, *pPsh, *pPsl, *pcwh, *pcwl;
    cudaGetSymbolAddress((void**)&pf1Th, g_f1Th);
    cudaGetSymbolAddress((void**)&pf1Tl, g_f1Tl);
    cudaGetSymbolAddress((void**)&pf2h,  g_f2h);
    cudaGetSymbolAddress((void**)&pf2l,  g_f2l);
    cudaGetSymbolAddress((void**)&pATh,  g_ATh);
    cudaGetSymbolAddress((void**)&pATl,  g_ATl);
    cudaGetSymbolAddress((void**)&pBsh,  g_Bsh);
    cudaGetSymbolAddress((void**)&pBsl,  g_Bsl);
    cudaGetSymbolAddress((void**)&pPsh,  g_Psh);
    cudaGetSymbolAddress((void**)&pPsl,  g_Psl);
    cudaGetSymbolAddress((void**)&pcwh,  g_cwh);
    cudaGetSymbolAddress((void**)&pcwl,  g_cwl);

    static bool attr_set = false;
    if (!attr_set) {
        cudaFuncSetAttribute(gemm_mma, cudaFuncAttributeMaxDynamicSharedMemorySize, DSMEM_BYTES);
        attr_set = true;
    }

    // init + operand prep
    k_identity<<<4096, 256>>>();
    k_zero_m1<<<4096, 256>>>();
    k_zero_small<<<8, 1024>>>();
    k_c<<<1024, 128>>>(fc1_b, fc2_W, fc2_b);
    k_splitX<<<NROWS, 256>>>(x);
    k_tsplit<<<dim3(DDIM / 32, HDIM / 32), dim3(32, 8)>>>(fc1_W, HDIM, DDIM, pf1Th, pf1Tl);
    k_split<<<(DDIM * HDIM) / 1024, 256>>>(fc2_W, (size_t)DDIM * HDIM, pf2h, pf2l);
    k_split<<<(NLAY * DD) / 1024, 256>>>(comp_W, (size_t)NLAY * DD, pcwh, pcwl);

    // A = fc1^T @ fc2^T : A[i][j] = sum_h fc1T[i][h] * fc2_W[j][h]
    gemm_sq<<<dim3(16, 16), 128>>>(HDIM, pf1Th, pf1Tl, pf2h, pf2l,
                                   pA, DDIM, nullptr, nullptr);
    // A^T split (B-operand for the P chain)
    k_tsplit<<<dim3(32, 32), dim3(32, 8)>>>(pA, DDIM, DDIM, pATh, pATl);

    for (int i = 0; i < NLAY; i++) {
        // P = B @ A  (B-op = A^T), emits P split directly
        gemm_sq<<<dim3(16, 16), 128>>>(DDIM, pBsh, pBsl, pATh, pATl,
                                       pP, DDIM, pPsh, pPsl);
        // C_i = P @ comp_W[i]^T  (B-op = comp_W[i] row-major) -> Wbig block i
        gemm_sq<<<dim3(16, 16), 128>>>(DDIM, pPsh, pPsl,
                                       pcwh + (size_t)i * DD, pcwl + (size_t)i * DD,
                                       pW + i * DDIM, NTOT, nullptr, nullptr);
        k_gemv_u<<<dim3(4, 8), 256>>>();
        k_gemv_d<<<1024, 128>>>(comp_W + (size_t)i * DD, comp_b + i * DDIM, i);
        k_matupd<<<4096, 256>>>();
        k_vecupd<<<4, 256>>>();
    }
    k_finalize<<<4096, 256>>>();

    // split+transpose Wbig for the big tensor-core GEMM
    k_splitWT<<<dim3(NTOT / 32, DDIM / 32), dim3(32, 8)>>>();

    // the one big tensor-core GEMM: [out0..out4 | inv_total | nxt] = x @ Wbig + bias
    gemm_mma<<<dim3(NTOT / 128, NROWS / 128), 256, DSMEM_BYTES>>>(o_inv, o_nxt);

    // loss pipeline
    k_rowstats<<<NLAY * NROWS, 256>>>();
    k_loss<<<dim3(4, 64, NLAY), 256>>>();
    k_broadcast<<<4096, 256>>>(o_loss);
}